// round 4
// baseline (speedup 1.0000x reference)
#include <cuda_runtime.h>
#include <math.h>

#define Nn 50000
#define Ee 300000
#define Mm (Ee + Nn)
#define IND 64
#define Hh 256
#define Ll 4
#define NBc 181
#define Gg 64

// ---------------- scratch (device globals; no allocation allowed) ----------------
__device__ float g_x[Nn * Hh];
__device__ float g_xl[Nn * Hh];
__device__ float g_xr[Nn * Hh];
__device__ float g_out[Nn * Hh];
__device__ float g_e[Mm];
__device__ float g_nmax[Nn];
__device__ float g_nsum[Nn];
__device__ float g_gate[Nn];
__device__ float g_bmax[Gg];
__device__ float g_bsum[Gg];
__device__ float g_pooled[Gg * Hh];
__device__ int   g_src[Mm];
__device__ int   g_dst[Mm];
__device__ int   g_idx64;

// ---------------- helpers ----------------
__device__ __forceinline__ void atomicMaxF(float* addr, float val) {
    if (val >= 0.f) atomicMax((int*)addr, __float_as_int(val));
    else            atomicMin((unsigned int*)addr, __float_as_uint(val));
}

// Detect whether index tensors are int64 or int32 (values uniform in [0,50000)
// make the int64 interpretation of packed int32 pairs exceed Nn quickly).
__global__ void detect_kernel(const void* ei) {
    const long long* p = (const long long*)ei;
    int ok = 1;
    for (int i = 0; i < 64; i++) {
        long long v = p[i];
        if (v < 0 || v >= Nn) { ok = 0; break; }
    }
    g_idx64 = ok;
}

// Convert edge indices (+ self loops) to int32 once.
__global__ void convert_kernel(const void* ei) {
    int m = blockIdx.x * blockDim.x + threadIdx.x;
    if (m >= Mm) return;
    int is64 = g_idx64;
    int s, d;
    if (m < Ee) {
        if (is64) { s = (int)((const long long*)ei)[m]; d = (int)((const long long*)ei)[(long long)Ee + m]; }
        else      { s = ((const int*)ei)[m];            d = ((const int*)ei)[Ee + m]; }
    } else { s = d = m - Ee; }
    g_src[m] = s;
    g_dst[m] = d;
}

__global__ void fill4_kernel(float4* p, float v, int n4) {
    int i = blockIdx.x * blockDim.x + threadIdx.x;
    if (i < n4) p[i] = make_float4(v, v, v, v);
}

__global__ void init_node_kernel(float* nmax, float* nsum, int n) {
    int i = blockIdx.x * blockDim.x + threadIdx.x;
    if (i < n) { nmax[i] = -INFINITY; nsum[i] = 0.f; }
}

// ---------------- SGEMM:  C[n, 256] = A[n,K] @ W[256,K]^T + bias ----------------
// 128x128 block tile, 256 threads, 8x8 micro-tile, K-tile 16, smem double-buffer.
__global__ __launch_bounds__(256, 2)
void sgemm128_kernel(const float* __restrict__ A, const float* __restrict__ W,
                     const float* __restrict__ bias, float* __restrict__ C,
                     int n, int K, int relu) {
    __shared__ float As[2][16][132];
    __shared__ float Bs[2][16][132];
    const int tx   = threadIdx.x;
    const int row0 = blockIdx.y * 128;
    const int col0 = blockIdx.x * 128;
    const int tr = (tx >> 4) << 3;   // 0..120
    const int tc = (tx & 15) << 3;   // 0..120

    // global-load mapping: float4 id i in [0,512): row=i>>2, kq=i&3
    const int r_a0 = tx >> 2,  kq = (tx & 3) << 2;   // first f4: rows 0..63
    const int r_a1 = r_a0 + 64;                      // second f4: rows 64..127

    float acc[8][8];
#pragma unroll
    for (int i = 0; i < 8; i++)
#pragma unroll
        for (int j = 0; j < 8; j++) acc[i][j] = 0.f;

    const int stages = K >> 4;

    // prologue: load stage 0
    {
        int gr0 = row0 + r_a0, gr1 = row0 + r_a1;
        float4 a0 = (gr0 < n) ? *(const float4*)&A[(size_t)gr0 * K + kq] : make_float4(0,0,0,0);
        float4 a1 = (gr1 < n) ? *(const float4*)&A[(size_t)gr1 * K + kq] : make_float4(0,0,0,0);
        float4 b0 = *(const float4*)&W[(size_t)(col0 + r_a0) * K + kq];
        float4 b1 = *(const float4*)&W[(size_t)(col0 + r_a1) * K + kq];
        As[0][kq+0][r_a0]=a0.x; As[0][kq+1][r_a0]=a0.y; As[0][kq+2][r_a0]=a0.z; As[0][kq+3][r_a0]=a0.w;
        As[0][kq+0][r_a1]=a1.x; As[0][kq+1][r_a1]=a1.y; As[0][kq+2][r_a1]=a1.z; As[0][kq+3][r_a1]=a1.w;
        Bs[0][kq+0][r_a0]=b0.x; Bs[0][kq+1][r_a0]=b0.y; Bs[0][kq+2][r_a0]=b0.z; Bs[0][kq+3][r_a0]=b0.w;
        Bs[0][kq+0][r_a1]=b1.x; Bs[0][kq+1][r_a1]=b1.y; Bs[0][kq+2][r_a1]=b1.z; Bs[0][kq+3][r_a1]=b1.w;
    }
    __syncthreads();

    int buf = 0;
    for (int s = 0; s < stages; s++) {
        float4 a0, a1, b0, b1;
        const int has_next = (s + 1 < stages);
        if (has_next) {
            int kt = (s + 1) << 4;
            int gr0 = row0 + r_a0, gr1 = row0 + r_a1;
            a0 = (gr0 < n) ? *(const float4*)&A[(size_t)gr0 * K + kt + kq] : make_float4(0,0,0,0);
            a1 = (gr1 < n) ? *(const float4*)&A[(size_t)gr1 * K + kt + kq] : make_float4(0,0,0,0);
            b0 = *(const float4*)&W[(size_t)(col0 + r_a0) * K + kt + kq];
            b1 = *(const float4*)&W[(size_t)(col0 + r_a1) * K + kt + kq];
        }
#pragma unroll
        for (int kk = 0; kk < 16; kk++) {
            float4 av0 = *(const float4*)&As[buf][kk][tr];
            float4 av1 = *(const float4*)&As[buf][kk][tr + 4];
            float4 bv0 = *(const float4*)&Bs[buf][kk][tc];
            float4 bv1 = *(const float4*)&Bs[buf][kk][tc + 4];
            float a[8] = {av0.x, av0.y, av0.z, av0.w, av1.x, av1.y, av1.z, av1.w};
            float b[8] = {bv0.x, bv0.y, bv0.z, bv0.w, bv1.x, bv1.y, bv1.z, bv1.w};
#pragma unroll
            for (int i = 0; i < 8; i++)
#pragma unroll
                for (int j = 0; j < 8; j++) acc[i][j] = fmaf(a[i], b[j], acc[i][j]);
        }
        if (has_next) {
            int nb = buf ^ 1;
            As[nb][kq+0][r_a0]=a0.x; As[nb][kq+1][r_a0]=a0.y; As[nb][kq+2][r_a0]=a0.z; As[nb][kq+3][r_a0]=a0.w;
            As[nb][kq+0][r_a1]=a1.x; As[nb][kq+1][r_a1]=a1.y; As[nb][kq+2][r_a1]=a1.z; As[nb][kq+3][r_a1]=a1.w;
            Bs[nb][kq+0][r_a0]=b0.x; Bs[nb][kq+1][r_a0]=b0.y; Bs[nb][kq+2][r_a0]=b0.z; Bs[nb][kq+3][r_a0]=b0.w;
            Bs[nb][kq+0][r_a1]=b1.x; Bs[nb][kq+1][r_a1]=b1.y; Bs[nb][kq+2][r_a1]=b1.z; Bs[nb][kq+3][r_a1]=b1.w;
            __syncthreads();
            buf = nb;
        }
    }

#pragma unroll
    for (int i = 0; i < 8; i++) {
        int gr = row0 + tr + i;
        if (gr >= n) continue;
        float* crow = &C[(size_t)gr * Hh + col0 + tc];
        float4 o0, o1;
        o0.x = acc[i][0] + bias[col0+tc+0]; o0.y = acc[i][1] + bias[col0+tc+1];
        o0.z = acc[i][2] + bias[col0+tc+2]; o0.w = acc[i][3] + bias[col0+tc+3];
        o1.x = acc[i][4] + bias[col0+tc+4]; o1.y = acc[i][5] + bias[col0+tc+5];
        o1.z = acc[i][6] + bias[col0+tc+6]; o1.w = acc[i][7] + bias[col0+tc+7];
        if (relu) {
            o0.x=fmaxf(o0.x,0.f); o0.y=fmaxf(o0.y,0.f); o0.z=fmaxf(o0.z,0.f); o0.w=fmaxf(o0.w,0.f);
            o1.x=fmaxf(o1.x,0.f); o1.y=fmaxf(o1.y,0.f); o1.z=fmaxf(o1.z,0.f); o1.w=fmaxf(o1.w,0.f);
        }
        *(float4*)&crow[0] = o0;
        *(float4*)&crow[4] = o1;
    }
}

// ---------------- edge kernels (GATv2 attention) ----------------
__global__ void edge_e_kernel(const int* __restrict__ src, const int* __restrict__ dst,
                              const float4* __restrict__ xl, const float4* __restrict__ xr,
                              const float4* __restrict__ att4,
                              float* __restrict__ e, float* __restrict__ nmax) {
    int w = (blockIdx.x * blockDim.x + threadIdx.x) >> 5;
    int lane = threadIdx.x & 31;
    if (w >= Mm) return;
    int s = src[w], d = dst[w];
    const float4* pl = xl + (size_t)s * 64;
    const float4* pr = xr + (size_t)d * 64;
    float sum = 0.f;
#pragma unroll
    for (int j = lane; j < 64; j += 32) {
        float4 a = pl[j], b = pr[j], t = att4[j];
        float v;
        v = a.x + b.x; v = (v > 0.f) ? v : 0.2f * v; sum = fmaf(v, t.x, sum);
        v = a.y + b.y; v = (v > 0.f) ? v : 0.2f * v; sum = fmaf(v, t.y, sum);
        v = a.z + b.z; v = (v > 0.f) ? v : 0.2f * v; sum = fmaf(v, t.z, sum);
        v = a.w + b.w; v = (v > 0.f) ? v : 0.2f * v; sum = fmaf(v, t.w, sum);
    }
#pragma unroll
    for (int o = 16; o; o >>= 1) sum += __shfl_xor_sync(0xffffffffu, sum, o);
    if (lane == 0) {
        e[w] = sum;
        atomicMaxF(&nmax[d], sum);
    }
}

__global__ void edge_expsum_kernel(const int* __restrict__ dst, float* __restrict__ e,
                                   const float* __restrict__ nmax, float* __restrict__ nsum) {
    int m = blockIdx.x * blockDim.x + threadIdx.x;
    if (m >= Mm) return;
    int d = dst[m];
    float a = __expf(e[m] - nmax[d]);
    e[m] = a;
    atomicAdd(&nsum[d], a);
}

__global__ void edge_scatter_kernel(const int* __restrict__ src, const int* __restrict__ dst,
                                    const float* __restrict__ e, const float* __restrict__ nsum,
                                    const float4* __restrict__ xl, float* __restrict__ out) {
    int w = (blockIdx.x * blockDim.x + threadIdx.x) >> 5;
    int lane = threadIdx.x & 31;
    if (w >= Mm) return;
    int s = src[w], d = dst[w];
    float wgt = e[w] / nsum[d];
    const float4* pl = xl + (size_t)s * 64;
    float* po = out + (size_t)d * Hh;
#pragma unroll
    for (int j = lane; j < 64; j += 32) {
        float4 a = pl[j];
        int h = j << 2;
        atomicAdd(&po[h+0], wgt * a.x);
        atomicAdd(&po[h+1], wgt * a.y);
        atomicAdd(&po[h+2], wgt * a.z);
        atomicAdd(&po[h+3], wgt * a.w);
    }
}

// ---------------- layernorm + relu + residual (block per node) ----------------
__global__ void ln_kernel(const float* __restrict__ outbuf, const float* __restrict__ bias_c,
                          const float* __restrict__ lg, const float* __restrict__ lb,
                          float* __restrict__ x) {
    int i = blockIdx.x, t = threadIdx.x;
    __shared__ float red[8];
    float v = outbuf[(size_t)i * Hh + t] + bias_c[t];
    float s = v;
#pragma unroll
    for (int o = 16; o; o >>= 1) s += __shfl_xor_sync(0xffffffffu, s, o);
    if ((t & 31) == 0) red[t >> 5] = s;
    __syncthreads();
    float tot = 0.f;
#pragma unroll
    for (int k = 0; k < 8; k++) tot += red[k];
    float mu = tot * (1.f / Hh);
    float dd = v - mu;
    __syncthreads();
    s = dd * dd;
#pragma unroll
    for (int o = 16; o; o >>= 1) s += __shfl_xor_sync(0xffffffffu, s, o);
    if ((t & 31) == 0) red[t >> 5] = s;
    __syncthreads();
    tot = 0.f;
#pragma unroll
    for (int k = 0; k < 8; k++) tot += red[k];
    float var = tot * (1.f / Hh);
    float y = dd * rsqrtf(var + 1e-5f) * lg[t] + lb[t];
    size_t idx = (size_t)i * Hh + t;
    x[idx] = fmaxf(y, 0.f) + x[idx];
}

// ---------------- gate / pooling ----------------
__global__ void gate_kernel(const float4* __restrict__ hid, const float4* __restrict__ Wg2,
                            const float* __restrict__ bg2, const void* __restrict__ batch,
                            float* __restrict__ gate, float* __restrict__ bmax) {
    int w = (blockIdx.x * blockDim.x + threadIdx.x) >> 5;
    int lane = threadIdx.x & 31;
    if (w >= Nn) return;
    const float4* p = hid + (size_t)w * 64;
    float sum = 0.f;
#pragma unroll
    for (int j = lane; j < 64; j += 32) {
        float4 a = p[j], t = Wg2[j];
        sum = fmaf(a.x, t.x, fmaf(a.y, t.y, fmaf(a.z, t.z, fmaf(a.w, t.w, sum))));
    }
#pragma unroll
    for (int o = 16; o; o >>= 1) sum += __shfl_xor_sync(0xffffffffu, sum, o);
    if (lane == 0) {
        float v = sum + bg2[0];
        gate[w] = v;
        int b = g_idx64 ? (int)((const long long*)batch)[w] : ((const int*)batch)[w];
        atomicMaxF(&bmax[b], v);
    }
}

__global__ void gate_expsum_kernel(float* __restrict__ gate, const float* __restrict__ bmax,
                                   float* __restrict__ bsum, const void* __restrict__ batch) {
    int i = blockIdx.x * blockDim.x + threadIdx.x;
    if (i >= Nn) return;
    int b = g_idx64 ? (int)((const long long*)batch)[i] : ((const int*)batch)[i];
    float a = __expf(gate[i] - bmax[b]);
    gate[i] = a;
    atomicAdd(&bsum[b], a);
}

__global__ void pool_kernel(const float* __restrict__ gate, const float* __restrict__ bsum,
                            const void* __restrict__ batch, const float4* __restrict__ x,
                            float* __restrict__ pooled) {
    int w = (blockIdx.x * blockDim.x + threadIdx.x) >> 5;
    int lane = threadIdx.x & 31;
    if (w >= Nn) return;
    int b = g_idx64 ? (int)((const long long*)batch)[w] : ((const int*)batch)[w];
    float wg = gate[w] / bsum[b];
    const float4* px = x + (size_t)w * 64;
    float* pp = pooled + (size_t)b * Hh;
#pragma unroll
    for (int j = lane; j < 64; j += 32) {
        float4 a = px[j];
        int h = j << 2;
        atomicAdd(&pp[h+0], wg * a.x);
        atomicAdd(&pp[h+1], wg * a.y);
        atomicAdd(&pp[h+2], wg * a.z);
        atomicAdd(&pp[h+3], wg * a.w);
    }
}

// ---------------- head ----------------
__global__ void head_kernel(const float* __restrict__ pooled,
                            const float* __restrict__ Ws, const float* __restrict__ bs,
                            const float* __restrict__ Wc, const float* __restrict__ bc,
                            const float* __restrict__ Wr1, const float* __restrict__ br1,
                            const float* __restrict__ Wr2, const float* __restrict__ br2,
                            float* __restrict__ out) {
    int g = blockIdx.x, t = threadIdx.x;
    __shared__ float sp[Hh];
    __shared__ float sz[Hh];
    __shared__ float sr[128];
    sp[t] = pooled[(size_t)g * Hh + t];
    __syncthreads();
    float acc = bs[t];
#pragma unroll 8
    for (int k = 0; k < Hh; k++) acc = fmaf(sp[k], Ws[(size_t)t * Hh + k], acc);
    sz[t] = fmaxf(acc, 0.f);
    __syncthreads();
    if (t < NBc) {
        float a2 = bc[t];
#pragma unroll 8
        for (int k = 0; k < Hh; k++) a2 = fmaf(sz[k], Wc[(size_t)t * Hh + k], a2);
        out[(size_t)g * NBc + t] = a2;
    }
    if (t < 128) {
        float a3 = br1[t];
#pragma unroll 8
        for (int k = 0; k < Hh; k++) a3 = fmaf(sz[k], Wr1[(size_t)t * Hh + k], a3);
        sr[t] = fmaxf(a3, 0.f);
    }
    __syncthreads();
    if (t < 128) {
        float v = sr[t] * Wr2[t];
#pragma unroll
        for (int o = 16; o; o >>= 1) v += __shfl_xor_sync(0xffffffffu, v, o);
        if ((t & 31) == 0) sp[t >> 5] = v;
    }
    __syncthreads();
    if (t == 0) {
        float tot = sp[0] + sp[1] + sp[2] + sp[3] + br2[0];
        out[(size_t)Gg * NBc + g] = tanhf(tot);
    }
}

// ---------------- launch ----------------
extern "C" void kernel_launch(void* const* d_in, const int* in_sizes, int n_in,
                              void* d_out, int out_size) {
    const float* x_in   = (const float*)d_in[0];
    const void*  ei     = d_in[1];
    const void*  batch  = d_in[2];
    const float* W_in   = (const float*)d_in[3];
    const float* b_in   = (const float*)d_in[4];
    const float* Wl     = (const float*)d_in[5];
    const float* bl     = (const float*)d_in[6];
    const float* Wr     = (const float*)d_in[7];
    const float* br     = (const float*)d_in[8];
    const float* att    = (const float*)d_in[9];
    const float* bias_c = (const float*)d_in[10];
    const float* ln_g   = (const float*)d_in[11];
    const float* ln_b   = (const float*)d_in[12];
    const float* Wg1    = (const float*)d_in[13];
    const float* bg1    = (const float*)d_in[14];
    const float* Wg2    = (const float*)d_in[15];
    const float* bg2    = (const float*)d_in[16];
    const float* Ws     = (const float*)d_in[17];
    const float* bs     = (const float*)d_in[18];
    const float* Wc     = (const float*)d_in[19];
    const float* bc     = (const float*)d_in[20];
    const float* Wr1    = (const float*)d_in[21];
    const float* br1    = (const float*)d_in[22];
    const float* Wr2    = (const float*)d_in[23];
    const float* br2    = (const float*)d_in[24];
    float* out = (float*)d_out;

    float *px, *pxl, *pxr, *pout, *pe, *pnmax, *pnsum, *pgate, *pbmax, *pbsum, *ppooled;
    int *psrc, *pdst;
    cudaGetSymbolAddress((void**)&px,      g_x);
    cudaGetSymbolAddress((void**)&pxl,     g_xl);
    cudaGetSymbolAddress((void**)&pxr,     g_xr);
    cudaGetSymbolAddress((void**)&pout,    g_out);
    cudaGetSymbolAddress((void**)&pe,      g_e);
    cudaGetSymbolAddress((void**)&pnmax,   g_nmax);
    cudaGetSymbolAddress((void**)&pnsum,   g_nsum);
    cudaGetSymbolAddress((void**)&pgate,   g_gate);
    cudaGetSymbolAddress((void**)&pbmax,   g_bmax);
    cudaGetSymbolAddress((void**)&pbsum,   g_bsum);
    cudaGetSymbolAddress((void**)&ppooled, g_pooled);
    cudaGetSymbolAddress((void**)&psrc,    g_src);
    cudaGetSymbolAddress((void**)&pdst,    g_dst);

    const dim3 gemm_grid(Hh / 128, (Nn + 127) / 128);
    const int EDGE_BLOCKS = (Mm * 32 + 255) / 256;
    const int NODE_W_BLOCKS = (Nn * 32 + 255) / 256;

    detect_kernel<<<1, 1>>>(ei);
    convert_kernel<<<(Mm + 255) / 256, 256>>>(ei);

    // input projection
    sgemm128_kernel<<<gemm_grid, 256>>>(x_in, W_in, b_in, px, Nn, IND, 0);

    for (int l = 0; l < Ll; l++) {
        sgemm128_kernel<<<gemm_grid, 256>>>(px, Wl + (size_t)l * Hh * Hh, bl + l * Hh, pxl, Nn, Hh, 0);
        sgemm128_kernel<<<gemm_grid, 256>>>(px, Wr + (size_t)l * Hh * Hh, br + l * Hh, pxr, Nn, Hh, 0);
        init_node_kernel<<<(Nn + 255) / 256, 256>>>(pnmax, pnsum, Nn);
        fill4_kernel<<<(Nn * Hh / 4 + 255) / 256, 256>>>((float4*)pout, 0.f, Nn * Hh / 4);
        edge_e_kernel<<<EDGE_BLOCKS, 256>>>(psrc, pdst, (const float4*)pxl, (const float4*)pxr,
                                            (const float4*)(att + l * Hh), pe, pnmax);
        edge_expsum_kernel<<<(Mm + 255) / 256, 256>>>(pdst, pe, pnmax, pnsum);
        edge_scatter_kernel<<<EDGE_BLOCKS, 256>>>(psrc, pdst, pe, pnsum, (const float4*)pxl, pout);
        ln_kernel<<<Nn, Hh>>>(pout, bias_c + l * Hh, ln_g + l * Hh, ln_b + l * Hh, px);
    }

    // gate MLP hidden (reuse g_xl)
    sgemm128_kernel<<<gemm_grid, 256>>>(px, Wg1, bg1, pxl, Nn, Hh, 1);
    init_node_kernel<<<1, 64>>>(pbmax, pbsum, Gg);
    fill4_kernel<<<(Gg * Hh / 4 + 63) / 64, 64>>>((float4*)ppooled, 0.f, Gg * Hh / 4);
    gate_kernel<<<NODE_W_BLOCKS, 256>>>((const float4*)pxl, (const float4*)Wg2, bg2, batch, pgate, pbmax);
    gate_expsum_kernel<<<(Nn + 255) / 256, 256>>>(pgate, pbmax, pbsum, batch);
    pool_kernel<<<NODE_W_BLOCKS, 256>>>(pgate, pbsum, batch, (const float4*)px, ppooled);
    head_kernel<<<Gg, Hh>>>(ppooled, Ws, bs, Wc, bc, Wr1, br1, Wr2, br2, out);
}

// round 5
// speedup vs baseline: 1.5807x; 1.5807x over previous
#include <cuda_runtime.h>
#include <math.h>

#define Nn 50000
#define Ee 300000
#define Mm (Ee + Nn)
#define IND 64
#define Hh 256
#define Ll 4
#define NBc 181
#define Gg 64
#define SCANB 1024
#define NSCANB ((Nn + SCANB - 1) / SCANB)

// ---------------- scratch (device globals; no allocation allowed) ----------------
__device__ float g_x[Nn * Hh];
__device__ float g_xl[Nn * Hh];
__device__ float g_xr[Nn * Hh];
__device__ float g_gate[Nn];
__device__ float g_pooled[Gg * Hh];
__device__ int   g_src[Mm];
__device__ int   g_dst[Mm];
__device__ int   g_deg[Nn];
__device__ int   g_incl[Nn];
__device__ int   g_bsum[NSCANB];
__device__ int   g_rowptr[Nn + 1];
__device__ int   g_cursor[Nn];
__device__ int   g_csrsrc[Mm];
__device__ int   g_bstart[Gg + 1];
__device__ int   g_idx64;

// ---------------- index width detection ----------------
__global__ void detect_kernel(const void* ei) {
    const long long* p = (const long long*)ei;
    int ok = 1;
    for (int i = 0; i < 64; i++) {
        long long v = p[i];
        if (v < 0 || v >= Nn) { ok = 0; break; }
    }
    g_idx64 = ok;
}

__global__ void zero_deg_kernel() {
    int i = blockIdx.x * blockDim.x + threadIdx.x;
    if (i < Nn) g_deg[i] = 0;
}

// decode edges (+self loops) to int32, count degrees by dst
__global__ void convert_count_kernel(const void* ei) {
    int m = blockIdx.x * blockDim.x + threadIdx.x;
    if (m >= Mm) return;
    int is64 = g_idx64;
    int s, d;
    if (m < Ee) {
        if (is64) { s = (int)((const long long*)ei)[m]; d = (int)((const long long*)ei)[(long long)Ee + m]; }
        else      { s = ((const int*)ei)[m];            d = ((const int*)ei)[Ee + m]; }
    } else { s = d = m - Ee; }
    g_src[m] = s;
    g_dst[m] = d;
    atomicAdd(&g_deg[d], 1);
}

// ---------------- exclusive scan over degrees (3 kernels) ----------------
__global__ void scan1_kernel() {
    __shared__ int sm[SCANB];
    int i = blockIdx.x * SCANB + threadIdx.x;
    int v = (i < Nn) ? g_deg[i] : 0;
    sm[threadIdx.x] = v;
    __syncthreads();
    for (int o = 1; o < SCANB; o <<= 1) {
        int t = (threadIdx.x >= o) ? sm[threadIdx.x - o] : 0;
        __syncthreads();
        sm[threadIdx.x] += t;
        __syncthreads();
    }
    if (i < Nn) g_incl[i] = sm[threadIdx.x];
    if (threadIdx.x == SCANB - 1) g_bsum[blockIdx.x] = sm[SCANB - 1];
}

__global__ void scan2_kernel() {
    __shared__ int sm[64];
    int t = threadIdx.x;
    int v = (t < NSCANB) ? g_bsum[t] : 0;
    sm[t] = v;
    __syncthreads();
    for (int o = 1; o < 64; o <<= 1) {
        int u = (t >= o) ? sm[t - o] : 0;
        __syncthreads();
        sm[t] += u;
        __syncthreads();
    }
    if (t < NSCANB) g_bsum[t] = sm[t];
}

__global__ void scan3_kernel() {
    int i = blockIdx.x * blockDim.x + threadIdx.x;
    if (i >= Nn) return;
    int b = i >> 10;
    int excl = g_incl[i] - g_deg[i] + (b ? g_bsum[b - 1] : 0);
    g_rowptr[i] = excl;
    g_cursor[i] = excl;
    if (i == 0) g_rowptr[Nn] = Mm;
}

__global__ void csr_fill_kernel() {
    int m = blockIdx.x * blockDim.x + threadIdx.x;
    if (m >= Mm) return;
    int d = g_dst[m];
    int pos = atomicAdd(&g_cursor[d], 1);
    g_csrsrc[pos] = g_src[m];
}

// ---------------- SGEMM:  C[n, 256] = A[n,K] @ W[256,K]^T + bias ----------------
__global__ __launch_bounds__(256, 2)
void sgemm128_kernel(const float* __restrict__ A, const float* __restrict__ W,
                     const float* __restrict__ bias, float* __restrict__ C,
                     int n, int K, int relu) {
    __shared__ float As[2][16][132];
    __shared__ float Bs[2][16][132];
    const int tx   = threadIdx.x;
    const int row0 = blockIdx.y * 128;
    const int col0 = blockIdx.x * 128;
    const int tr = (tx >> 4) << 3;
    const int tc = (tx & 15) << 3;
    const int r_a0 = tx >> 2,  kq = (tx & 3) << 2;
    const int r_a1 = r_a0 + 64;

    float acc[8][8];
#pragma unroll
    for (int i = 0; i < 8; i++)
#pragma unroll
        for (int j = 0; j < 8; j++) acc[i][j] = 0.f;

    const int stages = K >> 4;
    {
        int gr0 = row0 + r_a0, gr1 = row0 + r_a1;
        float4 a0 = (gr0 < n) ? *(const float4*)&A[(size_t)gr0 * K + kq] : make_float4(0,0,0,0);
        float4 a1 = (gr1 < n) ? *(const float4*)&A[(size_t)gr1 * K + kq] : make_float4(0,0,0,0);
        float4 b0 = *(const float4*)&W[(size_t)(col0 + r_a0) * K + kq];
        float4 b1 = *(const float4*)&W[(size_t)(col0 + r_a1) * K + kq];
        As[0][kq+0][r_a0]=a0.x; As[0][kq+1][r_a0]=a0.y; As[0][kq+2][r_a0]=a0.z; As[0][kq+3][r_a0]=a0.w;
        As[0][kq+0][r_a1]=a1.x; As[0][kq+1][r_a1]=a1.y; As[0][kq+2][r_a1]=a1.z; As[0][kq+3][r_a1]=a1.w;
        Bs[0][kq+0][r_a0]=b0.x; Bs[0][kq+1][r_a0]=b0.y; Bs[0][kq+2][r_a0]=b0.z; Bs[0][kq+3][r_a0]=b0.w;
        Bs[0][kq+0][r_a1]=b1.x; Bs[0][kq+1][r_a1]=b1.y; Bs[0][kq+2][r_a1]=b1.z; Bs[0][kq+3][r_a1]=b1.w;
    }
    __syncthreads();

    int buf = 0;
    for (int s = 0; s < stages; s++) {
        float4 a0, a1, b0, b1;
        const int has_next = (s + 1 < stages);
        if (has_next) {
            int kt = (s + 1) << 4;
            int gr0 = row0 + r_a0, gr1 = row0 + r_a1;
            a0 = (gr0 < n) ? *(const float4*)&A[(size_t)gr0 * K + kt + kq] : make_float4(0,0,0,0);
            a1 = (gr1 < n) ? *(const float4*)&A[(size_t)gr1 * K + kt + kq] : make_float4(0,0,0,0);
            b0 = *(const float4*)&W[(size_t)(col0 + r_a0) * K + kt + kq];
            b1 = *(const float4*)&W[(size_t)(col0 + r_a1) * K + kt + kq];
        }
#pragma unroll
        for (int kk = 0; kk < 16; kk++) {
            float4 av0 = *(const float4*)&As[buf][kk][tr];
            float4 av1 = *(const float4*)&As[buf][kk][tr + 4];
            float4 bv0 = *(const float4*)&Bs[buf][kk][tc];
            float4 bv1 = *(const float4*)&Bs[buf][kk][tc + 4];
            float a[8] = {av0.x, av0.y, av0.z, av0.w, av1.x, av1.y, av1.z, av1.w};
            float b[8] = {bv0.x, bv0.y, bv0.z, bv0.w, bv1.x, bv1.y, bv1.z, bv1.w};
#pragma unroll
            for (int i = 0; i < 8; i++)
#pragma unroll
                for (int j = 0; j < 8; j++) acc[i][j] = fmaf(a[i], b[j], acc[i][j]);
        }
        if (has_next) {
            int nb = buf ^ 1;
            As[nb][kq+0][r_a0]=a0.x; As[nb][kq+1][r_a0]=a0.y; As[nb][kq+2][r_a0]=a0.z; As[nb][kq+3][r_a0]=a0.w;
            As[nb][kq+0][r_a1]=a1.x; As[nb][kq+1][r_a1]=a1.y; As[nb][kq+2][r_a1]=a1.z; As[nb][kq+3][r_a1]=a1.w;
            Bs[nb][kq+0][r_a0]=b0.x; Bs[nb][kq+1][r_a0]=b0.y; Bs[nb][kq+2][r_a0]=b0.z; Bs[nb][kq+3][r_a0]=b0.w;
            Bs[nb][kq+0][r_a1]=b1.x; Bs[nb][kq+1][r_a1]=b1.y; Bs[nb][kq+2][r_a1]=b1.z; Bs[nb][kq+3][r_a1]=b1.w;
            __syncthreads();
            buf = nb;
        }
    }

#pragma unroll
    for (int i = 0; i < 8; i++) {
        int gr = row0 + tr + i;
        if (gr >= n) continue;
        float* crow = &C[(size_t)gr * Hh + col0 + tc];
        float4 o0, o1;
        o0.x = acc[i][0] + bias[col0+tc+0]; o0.y = acc[i][1] + bias[col0+tc+1];
        o0.z = acc[i][2] + bias[col0+tc+2]; o0.w = acc[i][3] + bias[col0+tc+3];
        o1.x = acc[i][4] + bias[col0+tc+4]; o1.y = acc[i][5] + bias[col0+tc+5];
        o1.z = acc[i][6] + bias[col0+tc+6]; o1.w = acc[i][7] + bias[col0+tc+7];
        if (relu) {
            o0.x=fmaxf(o0.x,0.f); o0.y=fmaxf(o0.y,0.f); o0.z=fmaxf(o0.z,0.f); o0.w=fmaxf(o0.w,0.f);
            o1.x=fmaxf(o1.x,0.f); o1.y=fmaxf(o1.y,0.f); o1.z=fmaxf(o1.z,0.f); o1.w=fmaxf(o1.w,0.f);
        }
        *(float4*)&crow[0] = o0;
        *(float4*)&crow[4] = o1;
    }
}

// ---------------- fused edge phase: warp per dst, online softmax + LN + residual --------
__global__ __launch_bounds__(256)
void edge_fused_kernel(const int* __restrict__ rowptr, const int* __restrict__ csrsrc,
                       const float4* __restrict__ xl, const float4* __restrict__ xr,
                       const float4* __restrict__ att4,
                       const float4* __restrict__ bias_c4,
                       const float4* __restrict__ lg4, const float4* __restrict__ lb4,
                       float4* __restrict__ x) {
    int d = (blockIdx.x * blockDim.x + threadIdx.x) >> 5;
    int lane = threadIdx.x & 31;
    if (d >= Nn) return;

    float4 r0 = xr[(size_t)d * 64 + lane];
    float4 r1 = xr[(size_t)d * 64 + 32 + lane];
    float4 t0 = att4[lane];
    float4 t1 = att4[32 + lane];

    float m = -INFINITY, s = 0.f;
    float4 acc0 = make_float4(0,0,0,0), acc1 = make_float4(0,0,0,0);

    int p0 = rowptr[d], p1 = rowptr[d + 1];
    for (int p = p0; p < p1; p++) {
        int src = csrsrc[p];
        float4 l0 = xl[(size_t)src * 64 + lane];
        float4 l1 = xl[(size_t)src * 64 + 32 + lane];
        float e = 0.f, v;
        v = l0.x + r0.x; v = (v > 0.f) ? v : 0.2f * v; e = fmaf(v, t0.x, e);
        v = l0.y + r0.y; v = (v > 0.f) ? v : 0.2f * v; e = fmaf(v, t0.y, e);
        v = l0.z + r0.z; v = (v > 0.f) ? v : 0.2f * v; e = fmaf(v, t0.z, e);
        v = l0.w + r0.w; v = (v > 0.f) ? v : 0.2f * v; e = fmaf(v, t0.w, e);
        v = l1.x + r1.x; v = (v > 0.f) ? v : 0.2f * v; e = fmaf(v, t1.x, e);
        v = l1.y + r1.y; v = (v > 0.f) ? v : 0.2f * v; e = fmaf(v, t1.y, e);
        v = l1.z + r1.z; v = (v > 0.f) ? v : 0.2f * v; e = fmaf(v, t1.z, e);
        v = l1.w + r1.w; v = (v > 0.f) ? v : 0.2f * v; e = fmaf(v, t1.w, e);
#pragma unroll
        for (int o = 16; o; o >>= 1) e += __shfl_xor_sync(0xffffffffu, e, o);
        // online softmax update
        float mn = fmaxf(m, e);
        float c = __expf(m - mn);   // first iter: exp(-inf)=0
        float w = __expf(e - mn);
        s = s * c + w;
        acc0.x = acc0.x * c + w * l0.x; acc0.y = acc0.y * c + w * l0.y;
        acc0.z = acc0.z * c + w * l0.z; acc0.w = acc0.w * c + w * l0.w;
        acc1.x = acc1.x * c + w * l1.x; acc1.y = acc1.y * c + w * l1.y;
        acc1.z = acc1.z * c + w * l1.z; acc1.w = acc1.w * c + w * l1.w;
        m = mn;
    }
    float inv = 1.f / s;
    float4 bc0 = bias_c4[lane], bc1 = bias_c4[32 + lane];
    float v0x = acc0.x * inv + bc0.x, v0y = acc0.y * inv + bc0.y;
    float v0z = acc0.z * inv + bc0.z, v0w = acc0.w * inv + bc0.w;
    float v1x = acc1.x * inv + bc1.x, v1y = acc1.y * inv + bc1.y;
    float v1z = acc1.z * inv + bc1.z, v1w = acc1.w * inv + bc1.w;

    // layernorm across the 256-wide row held by this warp
    float sum = v0x + v0y + v0z + v0w + v1x + v1y + v1z + v1w;
#pragma unroll
    for (int o = 16; o; o >>= 1) sum += __shfl_xor_sync(0xffffffffu, sum, o);
    float mu = sum * (1.f / Hh);
    float d0x = v0x - mu, d0y = v0y - mu, d0z = v0z - mu, d0w = v0w - mu;
    float d1x = v1x - mu, d1y = v1y - mu, d1z = v1z - mu, d1w = v1w - mu;
    float vsum = d0x*d0x + d0y*d0y + d0z*d0z + d0w*d0w + d1x*d1x + d1y*d1y + d1z*d1z + d1w*d1w;
#pragma unroll
    for (int o = 16; o; o >>= 1) vsum += __shfl_xor_sync(0xffffffffu, vsum, o);
    float rs = rsqrtf(vsum * (1.f / Hh) + 1e-5f);

    float4 lg0 = lg4[lane], lg1 = lg4[32 + lane];
    float4 lb0 = lb4[lane], lb1 = lb4[32 + lane];
    float4 xr0 = x[(size_t)d * 64 + lane];
    float4 xr1 = x[(size_t)d * 64 + 32 + lane];
    float4 o0, o1;
    o0.x = fmaxf(d0x * rs * lg0.x + lb0.x, 0.f) + xr0.x;
    o0.y = fmaxf(d0y * rs * lg0.y + lb0.y, 0.f) + xr0.y;
    o0.z = fmaxf(d0z * rs * lg0.z + lb0.z, 0.f) + xr0.z;
    o0.w = fmaxf(d0w * rs * lg0.w + lb0.w, 0.f) + xr0.w;
    o1.x = fmaxf(d1x * rs * lg1.x + lb1.x, 0.f) + xr1.x;
    o1.y = fmaxf(d1y * rs * lg1.y + lb1.y, 0.f) + xr1.y;
    o1.z = fmaxf(d1z * rs * lg1.z + lb1.z, 0.f) + xr1.z;
    o1.w = fmaxf(d1w * rs * lg1.w + lb1.w, 0.f) + xr1.w;
    x[(size_t)d * 64 + lane] = o0;
    x[(size_t)d * 64 + 32 + lane] = o1;
}

// ---------------- gate dot (no atomics) ----------------
__global__ void gate_dot_kernel(const float4* __restrict__ hid, const float4* __restrict__ Wg2,
                                const float* __restrict__ bg2, float* __restrict__ gate) {
    int w = (blockIdx.x * blockDim.x + threadIdx.x) >> 5;
    int lane = threadIdx.x & 31;
    if (w >= Nn) return;
    const float4* p = hid + (size_t)w * 64;
    float sum = 0.f;
#pragma unroll
    for (int j = lane; j < 64; j += 32) {
        float4 a = p[j], t = Wg2[j];
        sum = fmaf(a.x, t.x, fmaf(a.y, t.y, fmaf(a.z, t.z, fmaf(a.w, t.w, sum))));
    }
#pragma unroll
    for (int o = 16; o; o >>= 1) sum += __shfl_xor_sync(0xffffffffu, sum, o);
    if (lane == 0) gate[w] = sum + bg2[0];
}

// ---------------- batch segment boundaries (batch is sorted) ----------------
__global__ void bstart_kernel(const void* __restrict__ batch) {
    int g = threadIdx.x;
    if (g > Gg) return;
    if (g == Gg) { g_bstart[Gg] = Nn; return; }
    int is64 = g_idx64;
    int lo = 0, hi = Nn;
    while (lo < hi) {
        int mid = (lo + hi) >> 1;
        long long v = is64 ? ((const long long*)batch)[mid] : (long long)((const int*)batch)[mid];
        if (v < g) lo = mid + 1; else hi = mid;
    }
    g_bstart[g] = lo;
}

// ---------------- segmented softmax pooling (block per graph, contiguous) ----------------
__global__ __launch_bounds__(256)
void segpool_kernel(const float* __restrict__ gate, const float* __restrict__ x,
                    float* __restrict__ pooled) {
    int g = blockIdx.x, tid = threadIdx.x;
    int s = g_bstart[g], e = g_bstart[g + 1];
    __shared__ float red[8];
    __shared__ float ws[256];
    if (s >= e) { pooled[(size_t)g * Hh + tid] = 0.f; return; }

    float m = -INFINITY;
    for (int i = s + tid; i < e; i += 256) m = fmaxf(m, gate[i]);
#pragma unroll
    for (int o = 16; o; o >>= 1) m = fmaxf(m, __shfl_xor_sync(0xffffffffu, m, o));
    if ((tid & 31) == 0) red[tid >> 5] = m;
    __syncthreads();
    m = fmaxf(fmaxf(fmaxf(red[0], red[1]), fmaxf(red[2], red[3])),
              fmaxf(fmaxf(red[4], red[5]), fmaxf(red[6], red[7])));
    __syncthreads();

    float sum = 0.f;
    for (int i = s + tid; i < e; i += 256) sum += __expf(gate[i] - m);
#pragma unroll
    for (int o = 16; o; o >>= 1) sum += __shfl_xor_sync(0xffffffffu, sum, o);
    if ((tid & 31) == 0) red[tid >> 5] = sum;
    __syncthreads();
    sum = red[0] + red[1] + red[2] + red[3] + red[4] + red[5] + red[6] + red[7];
    __syncthreads();

    float acc = 0.f;
    for (int i0 = s; i0 < e; i0 += 256) {
        int n = min(256, e - i0);
        if (tid < n) ws[tid] = __expf(gate[i0 + tid] - m);
        __syncthreads();
        for (int j = 0; j < n; j++) acc = fmaf(ws[j], x[(size_t)(i0 + j) * Hh + tid], acc);
        __syncthreads();
    }
    pooled[(size_t)g * Hh + tid] = acc / sum;
}

// ---------------- head ----------------
__global__ void head_kernel(const float* __restrict__ pooled,
                            const float* __restrict__ Ws, const float* __restrict__ bs,
                            const float* __restrict__ Wc, const float* __restrict__ bc,
                            const float* __restrict__ Wr1, const float* __restrict__ br1,
                            const float* __restrict__ Wr2, const float* __restrict__ br2,
                            float* __restrict__ out) {
    int g = blockIdx.x, t = threadIdx.x;
    __shared__ float sp[Hh];
    __shared__ float sz[Hh];
    __shared__ float sr[128];
    sp[t] = pooled[(size_t)g * Hh + t];
    __syncthreads();
    float acc = bs[t];
#pragma unroll 8
    for (int k = 0; k < Hh; k++) acc = fmaf(sp[k], Ws[(size_t)t * Hh + k], acc);
    sz[t] = fmaxf(acc, 0.f);
    __syncthreads();
    if (t < NBc) {
        float a2 = bc[t];
#pragma unroll 8
        for (int k = 0; k < Hh; k++) a2 = fmaf(sz[k], Wc[(size_t)t * Hh + k], a2);
        out[(size_t)g * NBc + t] = a2;
    }
    if (t < 128) {
        float a3 = br1[t];
#pragma unroll 8
        for (int k = 0; k < Hh; k++) a3 = fmaf(sz[k], Wr1[(size_t)t * Hh + k], a3);
        sr[t] = fmaxf(a3, 0.f);
    }
    __syncthreads();
    if (t < 128) {
        float v = sr[t] * Wr2[t];
#pragma unroll
        for (int o = 16; o; o >>= 1) v += __shfl_xor_sync(0xffffffffu, v, o);
        if ((t & 31) == 0) sp[t >> 5] = v;
    }
    __syncthreads();
    if (t == 0) {
        float tot = sp[0] + sp[1] + sp[2] + sp[3] + br2[0];
        out[(size_t)Gg * NBc + g] = tanhf(tot);
    }
}

// ---------------- launch ----------------
extern "C" void kernel_launch(void* const* d_in, const int* in_sizes, int n_in,
                              void* d_out, int out_size) {
    const float* x_in   = (const float*)d_in[0];
    const void*  ei     = d_in[1];
    const void*  batch  = d_in[2];
    const float* W_in   = (const float*)d_in[3];
    const float* b_in   = (const float*)d_in[4];
    const float* Wl     = (const float*)d_in[5];
    const float* bl     = (const float*)d_in[6];
    const float* Wr     = (const float*)d_in[7];
    const float* br     = (const float*)d_in[8];
    const float* att    = (const float*)d_in[9];
    const float* bias_c = (const float*)d_in[10];
    const float* ln_g   = (const float*)d_in[11];
    const float* ln_b   = (const float*)d_in[12];
    const float* Wg1    = (const float*)d_in[13];
    const float* bg1    = (const float*)d_in[14];
    const float* Wg2    = (const float*)d_in[15];
    const float* bg2    = (const float*)d_in[16];
    const float* Ws     = (const float*)d_in[17];
    const float* bs     = (const float*)d_in[18];
    const float* Wc     = (const float*)d_in[19];
    const float* bc     = (const float*)d_in[20];
    const float* Wr1    = (const float*)d_in[21];
    const float* br1    = (const float*)d_in[22];
    const float* Wr2    = (const float*)d_in[23];
    const float* br2    = (const float*)d_in[24];
    float* out = (float*)d_out;

    float *px, *pxl, *pxr, *pgate, *ppooled;
    int *prowptr, *pcsrsrc;
    cudaGetSymbolAddress((void**)&px,      g_x);
    cudaGetSymbolAddress((void**)&pxl,     g_xl);
    cudaGetSymbolAddress((void**)&pxr,     g_xr);
    cudaGetSymbolAddress((void**)&pgate,   g_gate);
    cudaGetSymbolAddress((void**)&ppooled, g_pooled);
    cudaGetSymbolAddress((void**)&prowptr, g_rowptr);
    cudaGetSymbolAddress((void**)&pcsrsrc, g_csrsrc);

    const dim3 gemm_grid(Hh / 128, (Nn + 127) / 128);
    const int NODE_W_BLOCKS = (Nn * 32 + 255) / 256;

    // ---- CSR build (once per call) ----
    detect_kernel<<<1, 1>>>(ei);
    zero_deg_kernel<<<(Nn + 255) / 256, 256>>>();
    convert_count_kernel<<<(Mm + 255) / 256, 256>>>(ei);
    scan1_kernel<<<NSCANB, SCANB>>>();
    scan2_kernel<<<1, 64>>>();
    scan3_kernel<<<(Nn + 255) / 256, 256>>>();
    csr_fill_kernel<<<(Mm + 255) / 256, 256>>>();
    bstart_kernel<<<1, Gg + 1>>>(batch);

    // ---- input projection ----
    sgemm128_kernel<<<gemm_grid, 256>>>(x_in, W_in, b_in, px, Nn, IND, 0);

    // ---- GAT layers ----
    for (int l = 0; l < Ll; l++) {
        sgemm128_kernel<<<gemm_grid, 256>>>(px, Wl + (size_t)l * Hh * Hh, bl + l * Hh, pxl, Nn, Hh, 0);
        sgemm128_kernel<<<gemm_grid, 256>>>(px, Wr + (size_t)l * Hh * Hh, br + l * Hh, pxr, Nn, Hh, 0);
        edge_fused_kernel<<<NODE_W_BLOCKS, 256>>>(prowptr, pcsrsrc,
            (const float4*)pxl, (const float4*)pxr,
            (const float4*)(att + l * Hh),
            (const float4*)(bias_c + l * Hh),
            (const float4*)(ln_g + l * Hh), (const float4*)(ln_b + l * Hh),
            (float4*)px);
    }

    // ---- readout ----
    sgemm128_kernel<<<gemm_grid, 256>>>(px, Wg1, bg1, pxl, Nn, Hh, 1);
    gate_dot_kernel<<<NODE_W_BLOCKS, 256>>>((const float4*)pxl, (const float4*)Wg2, bg2, pgate);
    segpool_kernel<<<Gg, 256>>>(pgate, px, ppooled);
    head_kernel<<<Gg, Hh>>>(ppooled, Ws, bs, Wc, bc, Wr1, br1, Wr2, br2, out);
}

// round 8
// speedup vs baseline: 2.8282x; 1.7892x over previous
#include <cuda_runtime.h>
#include <cuda_bf16.h>
#include <math.h>
#include <stdint.h>

#define Nn 50000
#define Ee 300000
#define Mm (Ee + Nn)
#define IND 64
#define Hh 256
#define Ll 4
#define NBc 181
#define Gg 64
#define SCANB 1024
#define NSCANB ((Nn + SCANB - 1) / SCANB)

// ---------------- scratch (device globals; no allocation allowed) ----------------
__device__ float g_x[Nn * Hh];
__device__ float g_xl[Nn * Hh];
__device__ float g_xr[Nn * Hh];
__device__ float g_gate[Nn];
__device__ float g_pooled[Gg * Hh];
__device__ int   g_src[Mm];
__device__ int   g_dst[Mm];
__device__ int   g_deg[Nn];
__device__ int   g_incl[Nn];
__device__ int   g_bsum[NSCANB];
__device__ int   g_rowptr[Nn + 1];
__device__ int   g_cursor[Nn];
__device__ int   g_csrsrc[Mm];
__device__ int   g_bstart[Gg + 1];
__device__ int   g_idx64;

// ---------------- bf16 split helper ----------------
__device__ __forceinline__ void split2(float x, float y, uint32_t& hi, uint32_t& lo) {
    __nv_bfloat16 hx = __float2bfloat16_rn(x);
    __nv_bfloat16 hy = __float2bfloat16_rn(y);
    __nv_bfloat16 lx = __float2bfloat16_rn(x - __bfloat162float(hx));
    __nv_bfloat16 ly = __float2bfloat16_rn(y - __bfloat162float(hy));
    hi = ((uint32_t)__bfloat16_as_ushort(hy) << 16) | __bfloat16_as_ushort(hx);
    lo = ((uint32_t)__bfloat16_as_ushort(ly) << 16) | __bfloat16_as_ushort(lx);
}

__device__ __forceinline__ void mma16816(float* c, uint32_t a0, uint32_t a1, uint32_t a2, uint32_t a3,
                                         uint32_t b0, uint32_t b1) {
    asm volatile(
        "mma.sync.aligned.m16n8k16.row.col.f32.bf16.bf16.f32 "
        "{%0,%1,%2,%3}, {%4,%5,%6,%7}, {%8,%9}, {%0,%1,%2,%3};"
        : "+f"(c[0]), "+f"(c[1]), "+f"(c[2]), "+f"(c[3])
        : "r"(a0), "r"(a1), "r"(a2), "r"(a3), "r"(b0), "r"(b1));
}

// ---------------- tensor GEMM via mma.sync: C[n,256] = A[n,K]@W[256,K]^T + bias ----------
// CTA: 128 rows x 128 cols. 8 warps (4x2), warp tile 32x64 (2x8 m16n8k16).
// hi/lo bf16 split, 3 MMA terms -> ~fp32 accuracy.
#define KCH 64
#define RS 72        // padded smem row stride, bf16 units (144 B)
#define SM_AHI 0
#define SM_ALO 18432
#define SM_BHI 36864
#define SM_BLO 55296
#define SM_TOT 73728

__global__ __launch_bounds__(256, 2)
void gemm_mma_kernel(const float* __restrict__ A, const float* __restrict__ W,
                     const float* __restrict__ bias, float* __restrict__ C,
                     int n, int K, int relu) {
    extern __shared__ char sm[];
    const int tid = threadIdx.x;
    const int wid = tid >> 5, lane = tid & 31;
    const int row0 = blockIdx.y * 128;
    const int col0 = blockIdx.x * 128;
    const int wr = (wid & 3) * 32;        // warp row within CTA tile
    const int wc = (wid >> 2) * 64;       // warp col within CTA tile

    float acc[16][4];
#pragma unroll
    for (int t = 0; t < 16; t++)
#pragma unroll
        for (int q = 0; q < 4; q++) acc[t][q] = 0.f;

    const int lr = lane >> 2;             // 0..7
    const int lq = lane & 3;              // 0..3

    const int nchunk = K / KCH;
    for (int kc = 0; kc < nchunk; kc++) {
        // ---- load & split A chunk: 128 rows x 64 cols fp32 ----
#pragma unroll
        for (int it = 0; it < 8; it++) {
            int i = tid + it * 256;       // 2048 float4s
            int r = i >> 4, c4 = i & 15;
            int gr = row0 + r;
            float4 v = make_float4(0.f, 0.f, 0.f, 0.f);
            if (gr < n) v = *(const float4*)&A[(size_t)gr * K + kc * KCH + c4 * 4];
            uint32_t h0, l0, h1, l1;
            split2(v.x, v.y, h0, l0);
            split2(v.z, v.w, h1, l1);
            uint32_t off = (uint32_t)(r * (RS * 2) + c4 * 8);
            *(uint32_t*)(sm + SM_AHI + off)     = h0;
            *(uint32_t*)(sm + SM_AHI + off + 4) = h1;
            *(uint32_t*)(sm + SM_ALO + off)     = l0;
            *(uint32_t*)(sm + SM_ALO + off + 4) = l1;
        }
        // ---- load & split B chunk: 128 n-rows x 64 cols fp32 ----
#pragma unroll
        for (int it = 0; it < 8; it++) {
            int i = tid + it * 256;
            int r = i >> 4, c4 = i & 15;
            float4 v = *(const float4*)&W[(size_t)(col0 + r) * K + kc * KCH + c4 * 4];
            uint32_t h0, l0, h1, l1;
            split2(v.x, v.y, h0, l0);
            split2(v.z, v.w, h1, l1);
            uint32_t off = (uint32_t)(r * (RS * 2) + c4 * 8);
            *(uint32_t*)(sm + SM_BHI + off)     = h0;
            *(uint32_t*)(sm + SM_BHI + off + 4) = h1;
            *(uint32_t*)(sm + SM_BLO + off)     = l0;
            *(uint32_t*)(sm + SM_BLO + off + 4) = l1;
        }
        __syncthreads();

        // ---- compute: 4 k16 slabs ----
#pragma unroll
        for (int ks = 0; ks < 4; ks++) {
            const uint32_t kbyte = (uint32_t)((ks * 16 + lq * 2) * 2);
            // A fragments for both m-tiles (hi and lo)
            uint32_t ah[2][4], al[2][4];
#pragma unroll
            for (int mt = 0; mt < 2; mt++) {
                uint32_t base = (uint32_t)((wr + mt * 16 + lr) * (RS * 2)) + kbyte;
                ah[mt][0] = *(uint32_t*)(sm + SM_AHI + base);
                ah[mt][1] = *(uint32_t*)(sm + SM_AHI + base + 8 * (RS * 2));
                ah[mt][2] = *(uint32_t*)(sm + SM_AHI + base + 16);
                ah[mt][3] = *(uint32_t*)(sm + SM_AHI + base + 8 * (RS * 2) + 16);
                al[mt][0] = *(uint32_t*)(sm + SM_ALO + base);
                al[mt][1] = *(uint32_t*)(sm + SM_ALO + base + 8 * (RS * 2));
                al[mt][2] = *(uint32_t*)(sm + SM_ALO + base + 16);
                al[mt][3] = *(uint32_t*)(sm + SM_ALO + base + 8 * (RS * 2) + 16);
            }
#pragma unroll
            for (int nt = 0; nt < 8; nt++) {
                uint32_t nbase = (uint32_t)((wc + nt * 8 + lr) * (RS * 2)) + kbyte;
                uint32_t bh0 = *(uint32_t*)(sm + SM_BHI + nbase);
                uint32_t bh1 = *(uint32_t*)(sm + SM_BHI + nbase + 16);
                uint32_t bl0 = *(uint32_t*)(sm + SM_BLO + nbase);
                uint32_t bl1 = *(uint32_t*)(sm + SM_BLO + nbase + 16);
#pragma unroll
                for (int mt = 0; mt < 2; mt++) {
                    float* c = acc[mt * 8 + nt];
                    mma16816(c, ah[mt][0], ah[mt][1], ah[mt][2], ah[mt][3], bh0, bh1); // hi*hi
                    mma16816(c, ah[mt][0], ah[mt][1], ah[mt][2], ah[mt][3], bl0, bl1); // hi*lo
                    mma16816(c, al[mt][0], al[mt][1], al[mt][2], al[mt][3], bh0, bh1); // lo*hi
                }
            }
        }
        __syncthreads();
    }

    // ---- epilogue ----
#pragma unroll
    for (int mt = 0; mt < 2; mt++) {
#pragma unroll
        for (int nt = 0; nt < 8; nt++) {
            const float* c = acc[mt * 8 + nt];
            int col = col0 + wc + nt * 8 + lq * 2;
            float b0 = bias[col], b1 = bias[col + 1];
            int r0 = row0 + wr + mt * 16 + lr;
            int r1 = r0 + 8;
            if (r0 < n) {
                float2 o;
                o.x = c[0] + b0; o.y = c[1] + b1;
                if (relu) { o.x = fmaxf(o.x, 0.f); o.y = fmaxf(o.y, 0.f); }
                *(float2*)&C[(size_t)r0 * Hh + col] = o;
            }
            if (r1 < n) {
                float2 o;
                o.x = c[2] + b0; o.y = c[3] + b1;
                if (relu) { o.x = fmaxf(o.x, 0.f); o.y = fmaxf(o.y, 0.f); }
                *(float2*)&C[(size_t)r1 * Hh + col] = o;
            }
        }
    }
}

// ---------------- index width detection ----------------
__global__ void detect_kernel(const void* ei) {
    const long long* p = (const long long*)ei;
    int ok = 1;
    for (int i = 0; i < 64; i++) {
        long long v = p[i];
        if (v < 0 || v >= Nn) { ok = 0; break; }
    }
    g_idx64 = ok;
}

__global__ void zero_deg_kernel() {
    int i = blockIdx.x * blockDim.x + threadIdx.x;
    if (i < Nn) g_deg[i] = 0;
}

__global__ void convert_count_kernel(const void* ei) {
    int m = blockIdx.x * blockDim.x + threadIdx.x;
    if (m >= Mm) return;
    int is64 = g_idx64;
    int s, d;
    if (m < Ee) {
        if (is64) { s = (int)((const long long*)ei)[m]; d = (int)((const long long*)ei)[(long long)Ee + m]; }
        else      { s = ((const int*)ei)[m];            d = ((const int*)ei)[Ee + m]; }
    } else { s = d = m - Ee; }
    g_src[m] = s;
    g_dst[m] = d;
    atomicAdd(&g_deg[d], 1);
}

// ---------------- exclusive scan over degrees ----------------
__global__ void scan1_kernel() {
    __shared__ int sm[SCANB];
    int i = blockIdx.x * SCANB + threadIdx.x;
    int v = (i < Nn) ? g_deg[i] : 0;
    sm[threadIdx.x] = v;
    __syncthreads();
    for (int o = 1; o < SCANB; o <<= 1) {
        int t = (threadIdx.x >= o) ? sm[threadIdx.x - o] : 0;
        __syncthreads();
        sm[threadIdx.x] += t;
        __syncthreads();
    }
    if (i < Nn) g_incl[i] = sm[threadIdx.x];
    if (threadIdx.x == SCANB - 1) g_bsum[blockIdx.x] = sm[SCANB - 1];
}

__global__ void scan2_kernel() {
    __shared__ int sm[64];
    int t = threadIdx.x;
    int v = (t < NSCANB) ? g_bsum[t] : 0;
    sm[t] = v;
    __syncthreads();
    for (int o = 1; o < 64; o <<= 1) {
        int u = (t >= o) ? sm[t - o] : 0;
        __syncthreads();
        sm[t] += u;
        __syncthreads();
    }
    if (t < NSCANB) g_bsum[t] = sm[t];
}

__global__ void scan3_kernel() {
    int i = blockIdx.x * blockDim.x + threadIdx.x;
    if (i >= Nn) return;
    int b = i >> 10;
    int excl = g_incl[i] - g_deg[i] + (b ? g_bsum[b - 1] : 0);
    g_rowptr[i] = excl;
    g_cursor[i] = excl;
    if (i == 0) g_rowptr[Nn] = Mm;
}

__global__ void csr_fill_kernel() {
    int m = blockIdx.x * blockDim.x + threadIdx.x;
    if (m >= Mm) return;
    int d = g_dst[m];
    int pos = atomicAdd(&g_cursor[d], 1);
    g_csrsrc[pos] = g_src[m];
}

// ---------------- fused edge phase: warp per dst, online softmax + LN + residual --------
__global__ __launch_bounds__(256)
void edge_fused_kernel(const int* __restrict__ rowptr, const int* __restrict__ csrsrc,
                       const float4* __restrict__ xl, const float4* __restrict__ xr,
                       const float4* __restrict__ att4,
                       const float4* __restrict__ bias_c4,
                       const float4* __restrict__ lg4, const float4* __restrict__ lb4,
                       float4* __restrict__ x) {
    int d = (blockIdx.x * blockDim.x + threadIdx.x) >> 5;
    int lane = threadIdx.x & 31;
    if (d >= Nn) return;

    float4 r0 = xr[(size_t)d * 64 + lane];
    float4 r1 = xr[(size_t)d * 64 + 32 + lane];
    float4 t0 = att4[lane];
    float4 t1 = att4[32 + lane];

    float m = -INFINITY, s = 0.f;
    float4 acc0 = make_float4(0,0,0,0), acc1 = make_float4(0,0,0,0);

    int p0 = rowptr[d], p1 = rowptr[d + 1];
    for (int p = p0; p < p1; p++) {
        int src = csrsrc[p];
        float4 l0 = xl[(size_t)src * 64 + lane];
        float4 l1 = xl[(size_t)src * 64 + 32 + lane];
        float e = 0.f, v;
        v = l0.x + r0.x; v = (v > 0.f) ? v : 0.2f * v; e = fmaf(v, t0.x, e);
        v = l0.y + r0.y; v = (v > 0.f) ? v : 0.2f * v; e = fmaf(v, t0.y, e);
        v = l0.z + r0.z; v = (v > 0.f) ? v : 0.2f * v; e = fmaf(v, t0.z, e);
        v = l0.w + r0.w; v = (v > 0.f) ? v : 0.2f * v; e = fmaf(v, t0.w, e);
        v = l1.x + r1.x; v = (v > 0.f) ? v : 0.2f * v; e = fmaf(v, t1.x, e);
        v = l1.y + r1.y; v = (v > 0.f) ? v : 0.2f * v; e = fmaf(v, t1.y, e);
        v = l1.z + r1.z; v = (v > 0.f) ? v : 0.2f * v; e = fmaf(v, t1.z, e);
        v = l1.w + r1.w; v = (v > 0.f) ? v : 0.2f * v; e = fmaf(v, t1.w, e);
#pragma unroll
        for (int o = 16; o; o >>= 1) e += __shfl_xor_sync(0xffffffffu, e, o);
        float mn = fmaxf(m, e);
        float c = __expf(m - mn);
        float w = __expf(e - mn);
        s = s * c + w;
        acc0.x = acc0.x * c + w * l0.x; acc0.y = acc0.y * c + w * l0.y;
        acc0.z = acc0.z * c + w * l0.z; acc0.w = acc0.w * c + w * l0.w;
        acc1.x = acc1.x * c + w * l1.x; acc1.y = acc1.y * c + w * l1.y;
        acc1.z = acc1.z * c + w * l1.z; acc1.w = acc1.w * c + w * l1.w;
        m = mn;
    }
    float inv = 1.f / s;
    float4 bc0 = bias_c4[lane], bc1 = bias_c4[32 + lane];
    float v0x = acc0.x * inv + bc0.x, v0y = acc0.y * inv + bc0.y;
    float v0z = acc0.z * inv + bc0.z, v0w = acc0.w * inv + bc0.w;
    float v1x = acc1.x * inv + bc1.x, v1y = acc1.y * inv + bc1.y;
    float v1z = acc1.z * inv + bc1.z, v1w = acc1.w * inv + bc1.w;

    float sum = v0x + v0y + v0z + v0w + v1x + v1y + v1z + v1w;
#pragma unroll
    for (int o = 16; o; o >>= 1) sum += __shfl_xor_sync(0xffffffffu, sum, o);
    float mu = sum * (1.f / Hh);
    float d0x = v0x - mu, d0y = v0y - mu, d0z = v0z - mu, d0w = v0w - mu;
    float d1x = v1x - mu, d1y = v1y - mu, d1z = v1z - mu, d1w = v1w - mu;
    float vsum = d0x*d0x + d0y*d0y + d0z*d0z + d0w*d0w + d1x*d1x + d1y*d1y + d1z*d1z + d1w*d1w;
#pragma unroll
    for (int o = 16; o; o >>= 1) vsum += __shfl_xor_sync(0xffffffffu, vsum, o);
    float rs = rsqrtf(vsum * (1.f / Hh) + 1e-5f);

    float4 lg0 = lg4[lane], lg1 = lg4[32 + lane];
    float4 lb0 = lb4[lane], lb1 = lb4[32 + lane];
    float4 xr0 = x[(size_t)d * 64 + lane];
    float4 xr1 = x[(size_t)d * 64 + 32 + lane];
    float4 o0, o1;
    o0.x = fmaxf(d0x * rs * lg0.x + lb0.x, 0.f) + xr0.x;
    o0.y = fmaxf(d0y * rs * lg0.y + lb0.y, 0.f) + xr0.y;
    o0.z = fmaxf(d0z * rs * lg0.z + lb0.z, 0.f) + xr0.z;
    o0.w = fmaxf(d0w * rs * lg0.w + lb0.w, 0.f) + xr0.w;
    o1.x = fmaxf(d1x * rs * lg1.x + lb1.x, 0.f) + xr1.x;
    o1.y = fmaxf(d1y * rs * lg1.y + lb1.y, 0.f) + xr1.y;
    o1.z = fmaxf(d1z * rs * lg1.z + lb1.z, 0.f) + xr1.z;
    o1.w = fmaxf(d1w * rs * lg1.w + lb1.w, 0.f) + xr1.w;
    x[(size_t)d * 64 + lane] = o0;
    x[(size_t)d * 64 + 32 + lane] = o1;
}

// ---------------- gate dot ----------------
__global__ void gate_dot_kernel(const float4* __restrict__ hid, const float4* __restrict__ Wg2,
                                const float* __restrict__ bg2, float* __restrict__ gate) {
    int w = (blockIdx.x * blockDim.x + threadIdx.x) >> 5;
    int lane = threadIdx.x & 31;
    if (w >= Nn) return;
    const float4* p = hid + (size_t)w * 64;
    float sum = 0.f;
#pragma unroll
    for (int j = lane; j < 64; j += 32) {
        float4 a = p[j], t = Wg2[j];
        sum = fmaf(a.x, t.x, fmaf(a.y, t.y, fmaf(a.z, t.z, fmaf(a.w, t.w, sum))));
    }
#pragma unroll
    for (int o = 16; o; o >>= 1) sum += __shfl_xor_sync(0xffffffffu, sum, o);
    if (lane == 0) gate[w] = sum + bg2[0];
}

// ---------------- batch segment boundaries ----------------
__global__ void bstart_kernel(const void* __restrict__ batch) {
    int g = threadIdx.x;
    if (g > Gg) return;
    if (g == Gg) { g_bstart[Gg] = Nn; return; }
    int is64 = g_idx64;
    int lo = 0, hi = Nn;
    while (lo < hi) {
        int mid = (lo + hi) >> 1;
        long long v = is64 ? ((const long long*)batch)[mid] : (long long)((const int*)batch)[mid];
        if (v < g) lo = mid + 1; else hi = mid;
    }
    g_bstart[g] = lo;
}

// ---------------- segmented softmax pooling ----------------
__global__ __launch_bounds__(256)
void segpool_kernel(const float* __restrict__ gate, const float* __restrict__ x,
                    float* __restrict__ pooled) {
    int g = blockIdx.x, tid = threadIdx.x;
    int s = g_bstart[g], e = g_bstart[g + 1];
    __shared__ float red[8];
    __shared__ float ws[256];
    if (s >= e) { pooled[(size_t)g * Hh + tid] = 0.f; return; }

    float m = -INFINITY;
    for (int i = s + tid; i < e; i += 256) m = fmaxf(m, gate[i]);
#pragma unroll
    for (int o = 16; o; o >>= 1) m = fmaxf(m, __shfl_xor_sync(0xffffffffu, m, o));
    if ((tid & 31) == 0) red[tid >> 5] = m;
    __syncthreads();
    m = fmaxf(fmaxf(fmaxf(red[0], red[1]), fmaxf(red[2], red[3])),
              fmaxf(fmaxf(red[4], red[5]), fmaxf(red[6], red[7])));
    __syncthreads();

    float sum = 0.f;
    for (int i = s + tid; i < e; i += 256) sum += __expf(gate[i] - m);
#pragma unroll
    for (int o = 16; o; o >>= 1) sum += __shfl_xor_sync(0xffffffffu, sum, o);
    if ((tid & 31) == 0) red[tid >> 5] = sum;
    __syncthreads();
    sum = red[0] + red[1] + red[2] + red[3] + red[4] + red[5] + red[6] + red[7];
    __syncthreads();

    float acc = 0.f;
    for (int i0 = s; i0 < e; i0 += 256) {
        int n = min(256, e - i0);
        if (tid < n) ws[tid] = __expf(gate[i0 + tid] - m);
        __syncthreads();
        for (int j = 0; j < n; j++) acc = fmaf(ws[j], x[(size_t)(i0 + j) * Hh + tid], acc);
        __syncthreads();
    }
    pooled[(size_t)g * Hh + tid] = acc / sum;
}

// ---------------- head ----------------
__global__ void head_kernel(const float* __restrict__ pooled,
                            const float* __restrict__ Ws, const float* __restrict__ bs,
                            const float* __restrict__ Wc, const float* __restrict__ bc,
                            const float* __restrict__ Wr1, const float* __restrict__ br1,
                            const float* __restrict__ Wr2, const float* __restrict__ br2,
                            float* __restrict__ out) {
    int g = blockIdx.x, t = threadIdx.x;
    __shared__ float sp[Hh];
    __shared__ float sz[Hh];
    __shared__ float sr[128];
    sp[t] = pooled[(size_t)g * Hh + t];
    __syncthreads();
    float acc = bs[t];
#pragma unroll 8
    for (int k = 0; k < Hh; k++) acc = fmaf(sp[k], Ws[(size_t)t * Hh + k], acc);
    sz[t] = fmaxf(acc, 0.f);
    __syncthreads();
    if (t < NBc) {
        float a2 = bc[t];
#pragma unroll 8
        for (int k = 0; k < Hh; k++) a2 = fmaf(sz[k], Wc[(size_t)t * Hh + k], a2);
        out[(size_t)g * NBc + t] = a2;
    }
    if (t < 128) {
        float a3 = br1[t];
#pragma unroll 8
        for (int k = 0; k < Hh; k++) a3 = fmaf(sz[k], Wr1[(size_t)t * Hh + k], a3);
        sr[t] = fmaxf(a3, 0.f);
    }
    __syncthreads();
    if (t < 128) {
        float v = sr[t] * Wr2[t];
#pragma unroll
        for (int o = 16; o; o >>= 1) v += __shfl_xor_sync(0xffffffffu, v, o);
        if ((t & 31) == 0) sp[t >> 5] = v;
    }
    __syncthreads();
    if (t == 0) {
        float tot = sp[0] + sp[1] + sp[2] + sp[3] + br2[0];
        out[(size_t)Gg * NBc + g] = tanhf(tot);
    }
}

// ---------------- launch ----------------
extern "C" void kernel_launch(void* const* d_in, const int* in_sizes, int n_in,
                              void* d_out, int out_size) {
    const float* x_in   = (const float*)d_in[0];
    const void*  ei     = d_in[1];
    const void*  batch  = d_in[2];
    const float* W_in   = (const float*)d_in[3];
    const float* b_in   = (const float*)d_in[4];
    const float* Wl     = (const float*)d_in[5];
    const float* bl     = (const float*)d_in[6];
    const float* Wr     = (const float*)d_in[7];
    const float* br     = (const float*)d_in[8];
    const float* att    = (const float*)d_in[9];
    const float* bias_c = (const float*)d_in[10];
    const float* ln_g   = (const float*)d_in[11];
    const float* ln_b   = (const float*)d_in[12];
    const float* Wg1    = (const float*)d_in[13];
    const float* bg1    = (const float*)d_in[14];
    const float* Wg2    = (const float*)d_in[15];
    const float* bg2    = (const float*)d_in[16];
    const float* Ws     = (const float*)d_in[17];
    const float* bs     = (const float*)d_in[18];
    const float* Wc     = (const float*)d_in[19];
    const float* bc     = (const float*)d_in[20];
    const float* Wr1    = (const float*)d_in[21];
    const float* br1    = (const float*)d_in[22];
    const float* Wr2    = (const float*)d_in[23];
    const float* br2    = (const float*)d_in[24];
    float* out = (float*)d_out;

    float *px, *pxl, *pxr, *pgate, *ppooled;
    int *prowptr, *pcsrsrc;
    cudaGetSymbolAddress((void**)&px,      g_x);
    cudaGetSymbolAddress((void**)&pxl,     g_xl);
    cudaGetSymbolAddress((void**)&pxr,     g_xr);
    cudaGetSymbolAddress((void**)&pgate,   g_gate);
    cudaGetSymbolAddress((void**)&ppooled, g_pooled);
    cudaGetSymbolAddress((void**)&prowptr, g_rowptr);
    cudaGetSymbolAddress((void**)&pcsrsrc, g_csrsrc);

    cudaFuncSetAttribute(gemm_mma_kernel, cudaFuncAttributeMaxDynamicSharedMemorySize, SM_TOT);

    const dim3 gemm_grid(2, (Nn + 127) / 128);
    const int NODE_W_BLOCKS = (Nn * 32 + 255) / 256;

    // ---- CSR build ----
    detect_kernel<<<1, 1>>>(ei);
    zero_deg_kernel<<<(Nn + 255) / 256, 256>>>();
    convert_count_kernel<<<(Mm + 255) / 256, 256>>>(ei);
    scan1_kernel<<<NSCANB, SCANB>>>();
    scan2_kernel<<<1, 64>>>();
    scan3_kernel<<<(Nn + 255) / 256, 256>>>();
    csr_fill_kernel<<<(Mm + 255) / 256, 256>>>();
    bstart_kernel<<<1, Gg + 1>>>(batch);

    // ---- input projection (K=64) ----
    gemm_mma_kernel<<<gemm_grid, 256, SM_TOT>>>(x_in, W_in, b_in, px, Nn, IND, 0);

    // ---- GAT layers ----
    for (int l = 0; l < Ll; l++) {
        gemm_mma_kernel<<<gemm_grid, 256, SM_TOT>>>(px, Wl + (size_t)l * Hh * Hh, bl + l * Hh, pxl, Nn, Hh, 0);
        gemm_mma_kernel<<<gemm_grid, 256, SM_TOT>>>(px, Wr + (size_t)l * Hh * Hh, br + l * Hh, pxr, Nn, Hh, 0);
        edge_fused_kernel<<<NODE_W_BLOCKS, 256>>>(prowptr, pcsrsrc,
            (const float4*)pxl, (const float4*)pxr,
            (const float4*)(att + l * Hh),
            (const float4*)(bias_c + l * Hh),
            (const float4*)(ln_g + l * Hh), (const float4*)(ln_b + l * Hh),
            (float4*)px);
    }

    // ---- readout ----
    gemm_mma_kernel<<<gemm_grid, 256, SM_TOT>>>(px, Wg1, bg1, pxl, Nn, Hh, 1);
    gate_dot_kernel<<<NODE_W_BLOCKS, 256>>>((const float4*)pxl, (const float4*)Wg2, bg2, pgate);
    segpool_kernel<<<Gg, 256>>>(pgate, px, ppooled);
    head_kernel<<<Gg, Hh>>>(ppooled, Ws, bs, Wc, bc, Wr1, br1, Wr2, br2, out);
}